// round 8
// baseline (speedup 1.0000x reference)
#include <cuda_runtime.h>
#include <cuda_bf16.h>
#include <math.h>
#include <stdint.h>

// Problem constants: B=4, T=16, T0=12, L=64, C=512, H=8, hd=64, NUM_SEEDS=4

// ---------------- scratch (static device globals; no allocations) -----------
__device__ int g_maskn[64];                // normalized ctx_mask [b*16 + t]

// input splits (hi/lo bf16)
__device__ __align__(16) __nv_bfloat16 g_xh [3072 * 512], g_xl [3072 * 512];
__device__ __align__(16) __nv_bfloat16 g_xch[4096 * 512], g_xcl[4096 * 512];
__device__ __align__(16) __nv_bfloat16 g_dxh[4096 * 512], g_dxl[4096 * 512];
__device__ __align__(16) __nv_bfloat16 g_qwh[1536 * 512], g_qwl[1536 * 512];
__device__ __align__(16) __nv_bfloat16 g_kwh[ 512 * 512], g_kwl[ 512 * 512];
__device__ __align__(16) __nv_bfloat16 g_vwh[ 512 * 512], g_vwl[ 512 * 512];
__device__ __align__(16) __nv_bfloat16 g_pwh[ 512 * 512], g_pwl[ 512 * 512];
// intermediate GEMM outputs (hi/lo bf16)
__device__ __align__(16) __nv_bfloat16 g_qkvh[3072 * 1536], g_qkvl[3072 * 1536];
__device__ __align__(16) __nv_bfloat16 g_kcth[4096 * 512],  g_kctl[4096 * 512];
__device__ __align__(16) __nv_bfloat16 g_vcth[4096 * 512],  g_vctl[4096 * 512];
// attention output (hi/lo bf16)
__device__ __align__(16) __nv_bfloat16 g_ah [3072 * 512], g_al [3072 * 512];

// ---------------- helpers ----------------------------------------------------
__device__ __forceinline__ uint32_t s2u(const void* p) {
    uint32_t a;
    asm("{ .reg .u64 t; cvta.to.shared.u64 t, %1; cvt.u32.u64 %0, t; }"
        : "=r"(a) : "l"(p));
    return a;
}
__device__ __forceinline__ void cp16(uint32_t dst, const void* src) {
    asm volatile("cp.async.cg.shared.global [%0], [%1], 16;"
                 :: "r"(dst), "l"(src));
}
__device__ __forceinline__ void ldm_x4(uint32_t* r, uint32_t addr) {
    asm volatile("ldmatrix.sync.aligned.m8n8.x4.shared.b16 {%0,%1,%2,%3}, [%4];"
                 : "=r"(r[0]), "=r"(r[1]), "=r"(r[2]), "=r"(r[3]) : "r"(addr));
}
__device__ __forceinline__ void ldm_x4t(uint32_t* r, uint32_t addr) {
    asm volatile("ldmatrix.sync.aligned.m8n8.x4.trans.shared.b16 {%0,%1,%2,%3}, [%4];"
                 : "=r"(r[0]), "=r"(r[1]), "=r"(r[2]), "=r"(r[3]) : "r"(addr));
}
__device__ __forceinline__ void mma_bf16(float* c, const uint32_t* a, const uint32_t* b) {
    asm volatile(
        "mma.sync.aligned.m16n8k16.row.col.f32.bf16.bf16.f32 "
        "{%0,%1,%2,%3}, {%4,%5,%6,%7}, {%8,%9}, {%0,%1,%2,%3};"
        : "+f"(c[0]), "+f"(c[1]), "+f"(c[2]), "+f"(c[3])
        : "r"(a[0]), "r"(a[1]), "r"(a[2]), "r"(a[3]), "r"(b[0]), "r"(b[1]));
}
__device__ __forceinline__ uint32_t pack_bf(__nv_bfloat16 a, __nv_bfloat16 b) {
    return (uint32_t)__bfloat16_as_ushort(a) | ((uint32_t)__bfloat16_as_ushort(b) << 16);
}
__device__ __forceinline__ uint32_t pack_hi(float x, float y, float& rx, float& ry) {
    __nv_bfloat16 hx = __float2bfloat16(x), hy = __float2bfloat16(y);
    rx = x - __bfloat162float(hx);
    ry = y - __bfloat162float(hy);
    return pack_bf(hx, hy);
}

// ---------------- fused split: fp32 -> hi/lo bf16 ----------------------------
struct SplitArgs {
    const float4* src[4];
    uint2* hi[4];
    uint2* lo[4];
    int n4[4];
};
__global__ __launch_bounds__(256)
void split_all(SplitArgs a) {
    const int arr = blockIdx.y;
    const int n4 = a.n4[arr];
    const float4* __restrict__ s = a.src[arr];
    uint2* __restrict__ hp = a.hi[arr];
    uint2* __restrict__ lp = a.lo[arr];
    const int step = gridDim.x * 256;
    for (int i = blockIdx.x * 256 + threadIdx.x; i < n4; i += step) {
        float4 v = s[i];
        __nv_bfloat16 h0 = __float2bfloat16(v.x), h1 = __float2bfloat16(v.y);
        __nv_bfloat16 h2 = __float2bfloat16(v.z), h3 = __float2bfloat16(v.w);
        __nv_bfloat16 l0 = __float2bfloat16(v.x - __bfloat162float(h0));
        __nv_bfloat16 l1 = __float2bfloat16(v.y - __bfloat162float(h1));
        __nv_bfloat16 l2 = __float2bfloat16(v.z - __bfloat162float(h2));
        __nv_bfloat16 l3 = __float2bfloat16(v.w - __bfloat162float(h3));
        hp[i] = make_uint2(pack_bf(h0, h1), pack_bf(h2, h3));
        lp[i] = make_uint2(pack_bf(l0, l1), pack_bf(l2, l3));
    }
}

// ---------------- mask normalization (dtype-robust) --------------------------
__global__ void normalize_mask_kernel(const unsigned char* __restrict__ m8) {
    __shared__ int flag;
    int i = threadIdx.x;
    if (i == 0) flag = 0;
    __syncthreads();
    if ((i & 3) != 0 && m8[i] != 0) atomicOr(&flag, 1);
    __syncthreads();
    int v;
    if (flag) v = (m8[i] != 0) ? 1 : 0;
    else      v = (((const int*)m8)[i] != 0) ? 1 : 0;
    g_maskn[i] = v;
}

// ---------------- tensor-core split-bf16 GEMM: C = A @ W^T (K=512) -----------
// BM=BN=128, BK=32, 4-stage cp.async pipeline, 8 warps (2m x 4n),
// warp tile 64x32. 3-term emulation: Ah*Bh + Ah*Bl + Al*Bh.
// Output: fp32 C (+bias) if Ch==null, else hi/lo bf16 (Ch, Cl).
#define PITCHB 80
#define TERM_B (128 * PITCHB)      // 10240 per term (128 rows x 32 bf16 + pad)
#define BUF_B  (4 * TERM_B)        // Ahi, Alo, Bhi, Blo = 40960
#define GEMM_SMEM (4 * BUF_B)      // 163840 (4 pipeline stages)

__global__ __launch_bounds__(256)
void gemm_tc(const __nv_bfloat16* __restrict__ Ah, const __nv_bfloat16* __restrict__ Al,
             const __nv_bfloat16* __restrict__ Wh, const __nv_bfloat16* __restrict__ Wl,
             const float* __restrict__ bias, float* __restrict__ C,
             __nv_bfloat16* __restrict__ Ch, __nv_bfloat16* __restrict__ Cl,
             int M, int N) {
    extern __shared__ char smem[];
    const uint32_t sb = s2u(smem);
    const int tid = threadIdx.x;
    const int wid = tid >> 5, lane = tid & 31;
    const int gid = lane >> 2, tig = lane & 3;
    const int bm = blockIdx.y * 128, bn = blockIdx.x * 128;
    const int wm = wid >> 2, wn = wid & 3;     // warp tile m=wm*64, n=wn*32

    float acc[4][4][4];
#pragma unroll
    for (int mf = 0; mf < 4; mf++)
#pragma unroll
        for (int nf = 0; nf < 4; nf++)
#pragma unroll
            for (int r = 0; r < 4; r++) acc[mf][nf][r] = 0.f;

    auto issue = [&](int c, int buf) {
        uint32_t base = sb + buf * BUF_B;
#pragma unroll
        for (int i = 0; i < 2; i++) {
            int f = tid + i * 256;
            int row = f >> 2, seg = f & 3;
            uint32_t d = base + row * PITCHB + seg * 16;
            const int ko = c * 32 + seg * 8;
            cp16(d,              Ah + (size_t)(bm + row) * 512 + ko);
            cp16(d + TERM_B,     Al + (size_t)(bm + row) * 512 + ko);
            cp16(d + 2 * TERM_B, Wh + (size_t)(bn + row) * 512 + ko);
            cp16(d + 3 * TERM_B, Wl + (size_t)(bn + row) * 512 + ko);
        }
        asm volatile("cp.async.commit_group;");
    };

    issue(0, 0); issue(1, 1); issue(2, 2);

    const uint32_t a_row16 = lane & 15;
    const uint32_t a_cofs  = (lane >> 4) * 16;
    const uint32_t b_nrow  = (lane & 7) + ((lane >> 4) & 1) * 8;
    const uint32_t b_kofs  = ((lane >> 3) & 1) * 16;

    for (int c = 0; c < 16; c++) {
        if (c <= 13)      asm volatile("cp.async.wait_group 2;");
        else if (c == 14) asm volatile("cp.async.wait_group 1;");
        else              asm volatile("cp.async.wait_group 0;");
        __syncthreads();
        if (c <= 12) issue(c + 3, (c + 3) & 3);

        const uint32_t abase = sb + (c & 3) * BUF_B;
        const uint32_t bbase = abase + 2 * TERM_B;

#pragma unroll
        for (int kf = 0; kf < 2; kf++) {
            uint32_t ah[4][4], al[4][4], bh[4][2], bl[4][2];
            const uint32_t kb = kf * 32;
#pragma unroll
            for (int mf = 0; mf < 4; mf++) {
                uint32_t ad = abase + (wm * 64 + mf * 16 + a_row16) * PITCHB
                            + a_cofs + kb;
                ldm_x4(ah[mf], ad);
                ldm_x4(al[mf], ad + TERM_B);
            }
#pragma unroll
            for (int pr = 0; pr < 2; pr++) {
                uint32_t bd = bbase + (wn * 32 + pr * 16 + b_nrow) * PITCHB
                            + b_kofs + kb;
                uint32_t th[4], tl[4];
                ldm_x4(th, bd);
                ldm_x4(tl, bd + TERM_B);
                bh[pr * 2 + 0][0] = th[0]; bh[pr * 2 + 0][1] = th[1];
                bh[pr * 2 + 1][0] = th[2]; bh[pr * 2 + 1][1] = th[3];
                bl[pr * 2 + 0][0] = tl[0]; bl[pr * 2 + 0][1] = tl[1];
                bl[pr * 2 + 1][0] = tl[2]; bl[pr * 2 + 1][1] = tl[3];
            }
#pragma unroll
            for (int mf = 0; mf < 4; mf++)
#pragma unroll
                for (int nf = 0; nf < 4; nf++) {
                    mma_bf16(acc[mf][nf], ah[mf], bh[nf]);
                    mma_bf16(acc[mf][nf], ah[mf], bl[nf]);
                    mma_bf16(acc[mf][nf], al[mf], bh[nf]);
                }
        }
    }

    if (Ch) {
#pragma unroll
        for (int mf = 0; mf < 4; mf++) {
#pragma unroll
            for (int nf = 0; nf < 4; nf++) {
                int row = bm + wm * 64 + mf * 16 + gid;
                int col = bn + wn * 32 + nf * 8 + tig * 2;
                float r0, r1, r2, r3;
                uint32_t h0 = pack_hi(acc[mf][nf][0], acc[mf][nf][1], r0, r1);
                uint32_t h1 = pack_hi(acc[mf][nf][2], acc[mf][nf][3], r2, r3);
                *(uint32_t*)&Ch[(size_t)row * N + col] = h0;
                *(uint32_t*)&Ch[(size_t)(row + 8) * N + col] = h1;
                *(uint32_t*)&Cl[(size_t)row * N + col] =
                    pack_bf(__float2bfloat16(r0), __float2bfloat16(r1));
                *(uint32_t*)&Cl[(size_t)(row + 8) * N + col] =
                    pack_bf(__float2bfloat16(r2), __float2bfloat16(r3));
            }
        }
    } else {
#pragma unroll
        for (int mf = 0; mf < 4; mf++) {
#pragma unroll
            for (int nf = 0; nf < 4; nf++) {
                int row = bm + wm * 64 + mf * 16 + gid;
                int col = bn + wn * 32 + nf * 8 + tig * 2;
                float b0 = bias ? bias[col] : 0.f;
                float b1 = bias ? bias[col + 1] : 0.f;
                float2 v0 = make_float2(acc[mf][nf][0] + b0, acc[mf][nf][1] + b1);
                float2 v1 = make_float2(acc[mf][nf][2] + b0, acc[mf][nf][3] + b1);
                *(float2*)&C[(size_t)row * N + col] = v0;
                *(float2*)&C[(size_t)(row + 8) * N + col] = v1;
            }
        }
    }
}

// ---------------- tensor-core flash attention (unchanged, validated) ---------
#define APITCH 144
#define TILE_B 9216
#define QH_OFF 0
#define QL_OFF TILE_B
#define KV_OFF (2 * TILE_B)
#define KVBUF_B (4 * TILE_B)
#define ATTN_SMEM (2 * TILE_B + 2 * KVBUF_B)   // 92160

__global__ __launch_bounds__(128)
void attn_tc(const __nv_bfloat16* __restrict__ qkvh, const __nv_bfloat16* __restrict__ qkvl,
             const __nv_bfloat16* __restrict__ kcth, const __nv_bfloat16* __restrict__ kctl,
             const __nv_bfloat16* __restrict__ vcth, const __nv_bfloat16* __restrict__ vctl,
             __nv_bfloat16* __restrict__ outh, __nv_bfloat16* __restrict__ outl) {
    extern __shared__ char smem[];
    const uint32_t sb = s2u(smem);
    const int t0 = blockIdx.x, h = blockIdx.y, b = blockIdx.z;
    const int tid = threadIdx.x;
    const int w = tid >> 5, lane = tid & 31;
    const int gid = lane >> 2, tig = lane & 3;

    int ids[17], nv = 0;
    for (int t = 0; t < 16; t++)
        if (g_maskn[b * 16 + t] && t != t0 + 4) ids[nv++] = t;
    ids[nv++] = 16;

    const int seg = tid & 7;
    const int r0 = tid >> 3;

    {
        const size_t base = (size_t)(b * 768 + t0 * 64) * 1536 + h * 64 + seg * 8;
#pragma unroll
        for (int i = 0; i < 4; i++) {
            int row = r0 + i * 16;
            uint32_t d = sb + row * APITCH + seg * 16;
            cp16(d + QH_OFF, qkvh + base + (size_t)row * 1536);
            cp16(d + QL_OFF, qkvl + base + (size_t)row * 1536);
        }
    }

    auto issueKV = [&](int id, int buf) {
        const __nv_bfloat16 *ksh, *ksl, *vsh, *vsl;
        size_t kbase, vbase, rs;
        if (id < 16) {
            rs = 512;
            kbase = (size_t)(b * 1024 + id * 64) * 512 + h * 64 + seg * 8;
            vbase = kbase;
            ksh = kcth; ksl = kctl; vsh = vcth; vsl = vctl;
        } else {
            rs = 1536;
            size_t rb = (size_t)(b * 768 + t0 * 64) * 1536 + h * 64 + seg * 8;
            kbase = rb + 512; vbase = rb + 1024;
            ksh = qkvh; ksl = qkvl; vsh = qkvh; vsl = qkvl;
        }
        uint32_t base = sb + KV_OFF + buf * KVBUF_B;
#pragma unroll
        for (int i = 0; i < 4; i++) {
            int row = r0 + i * 16;
            uint32_t d = base + row * APITCH + seg * 16;
            cp16(d,              ksh + kbase + (size_t)row * rs);
            cp16(d + TILE_B,     ksl + kbase + (size_t)row * rs);
            cp16(d + 2 * TILE_B, vsh + vbase + (size_t)row * rs);
            cp16(d + 3 * TILE_B, vsl + vbase + (size_t)row * rs);
        }
        asm volatile("cp.async.commit_group;");
    };

    issueKV(ids[0], 0);

    const uint32_t a_row16 = lane & 15;
    const uint32_t a_cofs  = (lane >> 4) * 16;
    const uint32_t b_nrow  = (lane & 7) + ((lane >> 4) & 1) * 8;
    const uint32_t b_kofs  = ((lane >> 3) & 1) * 16;
    const uint32_t v_krow = lane & 15;
    const uint32_t v_dofs = (lane >> 4) * 16;

    uint32_t qh[4][4], ql[4][4];
    float of[8][4];
#pragma unroll
    for (int f = 0; f < 8; f++)
#pragma unroll
        for (int r = 0; r < 4; r++) of[f][r] = 0.f;
    float m1 = -INFINITY, m2 = -INFINITY, l1 = 0.f, l2 = 0.f;

    for (int i = 0; i < nv; i++) {
        if (i + 1 < nv) {
            issueKV(ids[i + 1], (i + 1) & 1);
            asm volatile("cp.async.wait_group 1;");
        } else {
            asm volatile("cp.async.wait_group 0;");
        }
        __syncthreads();

        if (i == 0) {
#pragma unroll
            for (int kf = 0; kf < 4; kf++) {
                uint32_t ad = sb + (w * 16 + a_row16) * APITCH + a_cofs + kf * 32;
                ldm_x4(qh[kf], ad + QH_OFF);
                ldm_x4(ql[kf], ad + QL_OFF);
            }
        }

        const uint32_t kvb = sb + KV_OFF + (i & 1) * KVBUF_B;

        float sf[8][4];
#pragma unroll
        for (int f = 0; f < 8; f++)
#pragma unroll
            for (int r = 0; r < 4; r++) sf[f][r] = 0.f;

#pragma unroll
        for (int nfp = 0; nfp < 4; nfp++) {
#pragma unroll
            for (int kf = 0; kf < 4; kf++) {
                uint32_t th[4], tl[4];
                uint32_t kd = kvb + (nfp * 16 + b_nrow) * APITCH + b_kofs + kf * 32;
                ldm_x4(th, kd);
                ldm_x4(tl, kd + TILE_B);
                mma_bf16(sf[nfp * 2 + 0], qh[kf], &th[0]);
                mma_bf16(sf[nfp * 2 + 0], qh[kf], &tl[0]);
                mma_bf16(sf[nfp * 2 + 0], ql[kf], &th[0]);
                mma_bf16(sf[nfp * 2 + 1], qh[kf], &th[2]);
                mma_bf16(sf[nfp * 2 + 1], qh[kf], &tl[2]);
                mma_bf16(sf[nfp * 2 + 1], ql[kf], &th[2]);
            }
        }

        float cm1 = -INFINITY, cm2 = -INFINITY;
#pragma unroll
        for (int f = 0; f < 8; f++) {
            sf[f][0] *= 0.125f; sf[f][1] *= 0.125f;
            sf[f][2] *= 0.125f; sf[f][3] *= 0.125f;
            cm1 = fmaxf(cm1, fmaxf(sf[f][0], sf[f][1]));
            cm2 = fmaxf(cm2, fmaxf(sf[f][2], sf[f][3]));
        }
        cm1 = fmaxf(cm1, __shfl_xor_sync(0xffffffffu, cm1, 1));
        cm1 = fmaxf(cm1, __shfl_xor_sync(0xffffffffu, cm1, 2));
        cm2 = fmaxf(cm2, __shfl_xor_sync(0xffffffffu, cm2, 1));
        cm2 = fmaxf(cm2, __shfl_xor_sync(0xffffffffu, cm2, 2));
        float mn1 = fmaxf(m1, cm1), mn2 = fmaxf(m2, cm2);
        float f1 = __expf(m1 - mn1), f2 = __expf(m2 - mn2);
        float rs1 = 0.f, rs2 = 0.f;
#pragma unroll
        for (int f = 0; f < 8; f++) {
            sf[f][0] = __expf(sf[f][0] - mn1);
            sf[f][1] = __expf(sf[f][1] - mn1);
            sf[f][2] = __expf(sf[f][2] - mn2);
            sf[f][3] = __expf(sf[f][3] - mn2);
            rs1 += sf[f][0] + sf[f][1];
            rs2 += sf[f][2] + sf[f][3];
        }
        rs1 += __shfl_xor_sync(0xffffffffu, rs1, 1);
        rs1 += __shfl_xor_sync(0xffffffffu, rs1, 2);
        rs2 += __shfl_xor_sync(0xffffffffu, rs2, 1);
        rs2 += __shfl_xor_sync(0xffffffffu, rs2, 2);
        l1 = l1 * f1 + rs1; l2 = l2 * f2 + rs2;
        m1 = mn1; m2 = mn2;
#pragma unroll
        for (int f = 0; f < 8; f++) {
            of[f][0] *= f1; of[f][1] *= f1;
            of[f][2] *= f2; of[f][3] *= f2;
        }

        uint32_t ph[4][4], pl[4][4];
#pragma unroll
        for (int kf = 0; kf < 4; kf++) {
            float r0a, r1a, r2a, r3a;
            ph[kf][0] = pack_hi(sf[2 * kf][0], sf[2 * kf][1], r0a, r1a);
            pl[kf][0] = pack_bf(__float2bfloat16(r0a), __float2bfloat16(r1a));
            ph[kf][1] = pack_hi(sf[2 * kf][2], sf[2 * kf][3], r0a, r1a);
            pl[kf][1] = pack_bf(__float2bfloat16(r0a), __float2bfloat16(r1a));
            ph[kf][2] = pack_hi(sf[2 * kf + 1][0], sf[2 * kf + 1][1], r2a, r3a);
            pl[kf][2] = pack_bf(__float2bfloat16(r2a), __float2bfloat16(r3a));
            ph[kf][3] = pack_hi(sf[2 * kf + 1][2], sf[2 * kf + 1][3], r2a, r3a);
            pl[kf][3] = pack_bf(__float2bfloat16(r2a), __float2bfloat16(r3a));
        }

        const uint32_t vb = kvb + 2 * TILE_B;
#pragma unroll
        for (int nfp = 0; nfp < 4; nfp++) {
#pragma unroll
            for (int kf = 0; kf < 4; kf++) {
                uint32_t vh_[4], vl_[4];
                uint32_t vd = vb + (kf * 16 + v_krow) * APITCH + nfp * 32 + v_dofs;
                ldm_x4t(vh_, vd);
                ldm_x4t(vl_, vd + TILE_B);
                mma_bf16(of[nfp * 2 + 0], ph[kf], &vh_[0]);
                mma_bf16(of[nfp * 2 + 0], ph[kf], &vl_[0]);
                mma_bf16(of[nfp * 2 + 0], pl[kf], &vh_[0]);
                mma_bf16(of[nfp * 2 + 1], ph[kf], &vh_[2]);
                mma_bf16(of[nfp * 2 + 1], ph[kf], &vl_[2]);
                mma_bf16(of[nfp * 2 + 1], pl[kf], &vh_[2]);
            }
        }
        __syncthreads();
    }

    const float inv1 = 1.0f / l1, inv2 = 1.0f / l2;
    const size_t row1 = (size_t)(b * 768 + t0 * 64 + w * 16 + gid);
    const size_t row2 = row1 + 8;
#pragma unroll
    for (int nf = 0; nf < 8; nf++) {
        int col = h * 64 + nf * 8 + tig * 2;
        float r0a, r1a;
        uint32_t h0 = pack_hi(of[nf][0] * inv1, of[nf][1] * inv1, r0a, r1a);
        *(uint32_t*)&outh[row1 * 512 + col] = h0;
        *(uint32_t*)&outl[row1 * 512 + col] =
            pack_bf(__float2bfloat16(r0a), __float2bfloat16(r1a));
        uint32_t h1 = pack_hi(of[nf][2] * inv2, of[nf][3] * inv2, r0a, r1a);
        *(uint32_t*)&outh[row2 * 512 + col] = h1;
        *(uint32_t*)&outl[row2 * 512 + col] =
            pack_bf(__float2bfloat16(r0a), __float2bfloat16(r1a));
    }
}

// ---------------- launcher ---------------------------------------------------
extern "C" void kernel_launch(void* const* d_in, const int* in_sizes, int n_in,
                              void* d_out, int out_size) {
    const float* x      = (const float*)d_in[0];
    const float* x_ctx  = (const float*)d_in[1];
    const float* dx_ctx = (const float*)d_in[2];
    const unsigned char* mask = (const unsigned char*)d_in[3];
    const float* qkv_w  = (const float*)d_in[4];
    const float* k_w    = (const float*)d_in[5];
    const float* v_w    = (const float*)d_in[6];
    const float* proj_w = (const float*)d_in[7];
    const float* proj_b = (const float*)d_in[8];
    float* out = (float*)d_out;

    __nv_bfloat16 *xh, *xl, *xch, *xcl, *dxh, *dxl, *qwh, *qwl,
                  *kwh, *kwl, *vwh, *vwl, *pwh, *pwl, *ah, *al,
                  *qkvh, *qkvl, *kcth, *kctl, *vcth, *vctl;
    cudaGetSymbolAddress((void**)&xh,  g_xh);  cudaGetSymbolAddress((void**)&xl,  g_xl);
    cudaGetSymbolAddress((void**)&xch, g_xch); cudaGetSymbolAddress((void**)&xcl, g_xcl);
    cudaGetSymbolAddress((void**)&dxh, g_dxh); cudaGetSymbolAddress((void**)&dxl, g_dxl);
    cudaGetSymbolAddress((void**)&qwh, g_qwh); cudaGetSymbolAddress((void**)&qwl, g_qwl);
    cudaGetSymbolAddress((void**)&kwh, g_kwh); cudaGetSymbolAddress((void**)&kwl, g_kwl);
    cudaGetSymbolAddress((void**)&vwh, g_vwh); cudaGetSymbolAddress((void**)&vwl, g_vwl);
    cudaGetSymbolAddress((void**)&pwh, g_pwh); cudaGetSymbolAddress((void**)&pwl, g_pwl);
    cudaGetSymbolAddress((void**)&ah,  g_ah);  cudaGetSymbolAddress((void**)&al,  g_al);
    cudaGetSymbolAddress((void**)&qkvh, g_qkvh); cudaGetSymbolAddress((void**)&qkvl, g_qkvl);
    cudaGetSymbolAddress((void**)&kcth, g_kcth); cudaGetSymbolAddress((void**)&kctl, g_kctl);
    cudaGetSymbolAddress((void**)&vcth, g_vcth); cudaGetSymbolAddress((void**)&vctl, g_vctl);

    cudaFuncSetAttribute(gemm_tc, cudaFuncAttributeMaxDynamicSharedMemorySize, GEMM_SMEM);
    cudaFuncSetAttribute(attn_tc, cudaFuncAttributeMaxDynamicSharedMemorySize, ATTN_SMEM);

    // 1: mask
    normalize_mask_kernel<<<1, 64>>>(mask);

    // 2: big splits (x, x_ctx, dx_ctx, qkv_w)
    SplitArgs sa;
    sa.src[0] = (const float4*)x;      sa.hi[0] = (uint2*)xh;  sa.lo[0] = (uint2*)xl;  sa.n4[0] = 3072 * 512 / 4;
    sa.src[1] = (const float4*)x_ctx;  sa.hi[1] = (uint2*)xch; sa.lo[1] = (uint2*)xcl; sa.n4[1] = 4096 * 512 / 4;
    sa.src[2] = (const float4*)dx_ctx; sa.hi[2] = (uint2*)dxh; sa.lo[2] = (uint2*)dxl; sa.n4[2] = 4096 * 512 / 4;
    sa.src[3] = (const float4*)qkv_w;  sa.hi[3] = (uint2*)qwh; sa.lo[3] = (uint2*)qwl; sa.n4[3] = 1536 * 512 / 4;
    split_all<<<dim3(296, 4), 256>>>(sa);

    // 3: small splits (k_w, v_w, proj_w)
    SplitArgs sb_;
    sb_.src[0] = (const float4*)k_w;    sb_.hi[0] = (uint2*)kwh; sb_.lo[0] = (uint2*)kwl; sb_.n4[0] = 512 * 512 / 4;
    sb_.src[1] = (const float4*)v_w;    sb_.hi[1] = (uint2*)vwh; sb_.lo[1] = (uint2*)vwl; sb_.n4[1] = 512 * 512 / 4;
    sb_.src[2] = (const float4*)proj_w; sb_.hi[2] = (uint2*)pwh; sb_.lo[2] = (uint2*)pwl; sb_.n4[2] = 512 * 512 / 4;
    sb_.src[3] = (const float4*)proj_w; sb_.hi[3] = (uint2*)pwh; sb_.lo[3] = (uint2*)pwl; sb_.n4[3] = 0;
    split_all<<<dim3(128, 3), 256>>>(sb_);

    // 4: qkv = x @ qkv_w^T -> hi/lo bf16
    gemm_tc<<<dim3(1536 / 128, 3072 / 128), 256, GEMM_SMEM>>>(
        xh, xl, qwh, qwl, nullptr, nullptr, qkvh, qkvl, 3072, 1536);
    // 5: k_ctx = dx_ctx @ k_w^T -> hi/lo bf16
    gemm_tc<<<dim3(512 / 128, 4096 / 128), 256, GEMM_SMEM>>>(
        dxh, dxl, kwh, kwl, nullptr, nullptr, kcth, kctl, 4096, 512);
    // 6: v_ctx = x_ctx @ v_w^T -> hi/lo bf16  (profiled launch)
    gemm_tc<<<dim3(512 / 128, 4096 / 128), 256, GEMM_SMEM>>>(
        xch, xcl, vwh, vwl, nullptr, nullptr, vcth, vctl, 4096, 512);

    // 7: tensor-core flash attention -> hi/lo bf16
    attn_tc<<<dim3(12, 8, 4), 128, ATTN_SMEM>>>(
        qkvh, qkvl, kcth, kctl, vcth, vctl, ah, al);

    // 8: final projection + bias -> d_out (fp32)
    gemm_tc<<<dim3(512 / 128, 3072 / 128), 256, GEMM_SMEM>>>(
        ah, al, pwh, pwl, proj_b, out, nullptr, nullptr, 3072, 512);
}